// round 1
// baseline (speedup 1.0000x reference)
#include <cuda_runtime.h>

// ---------------------------------------------------------------------------
// BiSpikeNet forward, single persistent kernel.
// T=8, B=16, F=C*H*W=262144.
//
// Strategy: 128 blocks (16 batches x 8 blocks/batch), 1024 threads each.
// Each block owns 32768 elements of one batch. Membrane state lives in SMEM
// (128 KiB), packed spike bits (8 steps) live in registers. The per-step
// per-batch mean(|m|) reduction uses deterministic block reductions + a
// software grid barrier (global atomic counters, reset by a prologue kernel
// each launch so graph replays are safe). Attention MLP ([16,8] summary ->
// softmax weights) is computed redundantly by warp 0 of each block.
// Global traffic: read x (128 MiB) + write out (16 MiB) only.
// ---------------------------------------------------------------------------

namespace {
constexpr int T_STEPS        = 8;
constexpr int BATCH          = 16;
constexpr int FDIM           = 1 << 18;          // 262144
constexpr int BLKS_PER_BATCH = 8;
constexpr int NBLOCKS        = BATCH * BLKS_PER_BATCH;   // 128
constexpr int NTHREADS       = 1024;
constexpr int EPB            = FDIM / BLKS_PER_BATCH;    // 32768 elems/block
constexpr int KG             = EPB / (NTHREADS * 4);     // 8 float4 groups/thread
constexpr int NHEADS         = 4;
constexpr int HID            = 64;
}

__device__ unsigned int g_bar[16];
__device__ float g_abs_part[T_STEPS][BATCH][BLKS_PER_BATCH];
__device__ int   g_cnt_part[T_STEPS][BATCH][BLKS_PER_BATCH];

__global__ void reset_kernel() {
    if (threadIdx.x < 16) g_bar[threadIdx.x] = 0u;
}

__global__ void __launch_bounds__(NTHREADS, 1) bispike_kernel(
    const float* __restrict__ x,
    const float* __restrict__ decay_p,
    const float* __restrict__ vth_p,
    const float* __restrict__ W1,
    const float* __restrict__ b1,
    const float* __restrict__ W2,
    const float* __restrict__ b2,
    const float* __restrict__ att_w,
    float* __restrict__ out)
{
    extern __shared__ float s_m[];               // EPB floats: membrane state
    __shared__ float s_red[32];
    __shared__ int   s_redi[32];
    __shared__ float s_h[NHEADS * HID];
    __shared__ float s_maps[32];
    __shared__ float s_aw[T_STEPS];
    __shared__ float s_invd;

    const int tid  = threadIdx.x;
    const int lane = tid & 31;
    const int warp = tid >> 5;
    const int b    = blockIdx.x >> 3;            // batch
    const int blk  = blockIdx.x & 7;             // slice within batch
    const int f0   = blk * EPB;

    const float d   = 1.0f / (1.0f + expf(-decay_p[0]));
    const float vth = vth_p[0];

    unsigned int bits4[KG];                      // 4 elements x 8 step-bits per word
#pragma unroll
    for (int k = 0; k < KG; k++) bits4[k] = 0u;

    float4* s_m4 = reinterpret_cast<float4*>(s_m);
    float inv_prev = 0.0f;

    // ---------------- temporal LIF loop ----------------
    for (int t = 0; t < T_STEPS; t++) {
        const float4* xp = reinterpret_cast<const float4*>(
            x + ((size_t)t * BATCH + b) * FDIM + f0);
        float sum_abs = 0.0f;
        int   cnt_prev = 0;
#pragma unroll
        for (int k = 0; k < KG; k++) {
            const int idx4 = k * NTHREADS + tid;
            float4 xv = xp[idx4];
            float xa[4] = {xv.x, xv.y, xv.z, xv.w};
            float ma[4];
            if (t == 0) {
#pragma unroll
                for (int j = 0; j < 4; j++) ma[j] = xa[j];
            } else {
                float4 mo = s_m4[idx4];
                float moa[4] = {mo.x, mo.y, mo.z, mo.w};
#pragma unroll
                for (int j = 0; j < 4; j++) {
                    float mn = moa[j] * inv_prev;   // normalized m_{t-1}
                    bool  sp = (mn >= vth);
                    float sf = sp ? 1.0f : 0.0f;
                    if (sp) { bits4[k] |= (1u << (8 * j + (t - 1))); cnt_prev++; }
                    ma[j] = d * (mn - vth * sf) + xa[j];
                }
            }
            s_m4[idx4] = make_float4(ma[0], ma[1], ma[2], ma[3]);
#pragma unroll
            for (int j = 0; j < 4; j++) sum_abs += fabsf(ma[j]);
        }

        // deterministic block reduction (|m| sum, previous-step spike count)
#pragma unroll
        for (int off = 16; off > 0; off >>= 1) {
            sum_abs  += __shfl_xor_sync(0xffffffffu, sum_abs, off);
            cnt_prev += __shfl_xor_sync(0xffffffffu, cnt_prev, off);
        }
        if (lane == 0) { s_red[warp] = sum_abs; s_redi[warp] = cnt_prev; }
        __syncthreads();
        if (warp == 0) {
            float v = s_red[lane];
            int   c = s_redi[lane];
#pragma unroll
            for (int off = 16; off > 0; off >>= 1) {
                v += __shfl_xor_sync(0xffffffffu, v, off);
                c += __shfl_xor_sync(0xffffffffu, c, off);
            }
            if (lane == 0) {
                g_abs_part[t][b][blk] = v;
                if (t > 0) g_cnt_part[t - 1][b][blk] = c;
                __threadfence();
                atomicAdd(&g_bar[t], 1u);
                volatile unsigned int* ctr = &g_bar[t];
                while (*ctr < (unsigned)NBLOCKS) __nanosleep(64);
                // deterministic 8-partial sum for this batch
                volatile float* pp = &g_abs_part[t][b][0];
                float tot = 0.0f;
#pragma unroll
                for (int i = 0; i < BLKS_PER_BATCH; i++) tot += pp[i];
                float denom = tot * (1.0f / (float)FDIM) + 1e-6f;
                s_invd = 1.0f / denom;
            }
        }
        __syncthreads();
        inv_prev = s_invd;
    }

    // ---------------- final step spikes (t = T-1) ----------------
    {
        int cnt = 0;
#pragma unroll
        for (int k = 0; k < KG; k++) {
            const int idx4 = k * NTHREADS + tid;
            float4 mo = s_m4[idx4];
            float moa[4] = {mo.x, mo.y, mo.z, mo.w};
#pragma unroll
            for (int j = 0; j < 4; j++) {
                if (moa[j] * inv_prev >= vth) {
                    bits4[k] |= (1u << (8 * j + 7));
                    cnt++;
                }
            }
        }
#pragma unroll
        for (int off = 16; off > 0; off >>= 1)
            cnt += __shfl_xor_sync(0xffffffffu, cnt, off);
        if (lane == 0) s_redi[warp] = cnt;
        __syncthreads();
        if (warp == 0) {
            int c = s_redi[lane];
#pragma unroll
            for (int off = 16; off > 0; off >>= 1)
                c += __shfl_xor_sync(0xffffffffu, c, off);
            if (lane == 0) {
                g_cnt_part[7][b][blk] = c;
                __threadfence();
                atomicAdd(&g_bar[8], 1u);
                volatile unsigned int* ctr = &g_bar[8];
                while (*ctr < (unsigned)NBLOCKS) __nanosleep(64);
            }
        }
        __syncthreads();
    }

    // ---------------- tiny attention MLP (warp 0, per batch) ----------------
    if (warp == 0) {
        float summ[T_STEPS];
#pragma unroll
        for (int t = 0; t < T_STEPS; t++) {
            volatile int* cp = &g_cnt_part[t][b][0];
            int tot = 0;
#pragma unroll
            for (int i = 0; i < BLKS_PER_BATCH; i++) tot += cp[i];
            summ[t] = (float)tot * (1.0f / (float)FDIM);
        }
        // h[n,hd] = relu(sum_t summ[t]*W1[n,hd,t] + b1[n,hd]); 256 vals, 8/lane
#pragma unroll
        for (int r = 0; r < 8; r++) {
            int idx = r * 32 + lane;
            float acc = b1[idx];
#pragma unroll
            for (int t = 0; t < T_STEPS; t++)
                acc += summ[t] * W1[idx * T_STEPS + t];
            s_h[idx] = fmaxf(acc, 0.0f);
        }
        __syncwarp();
        // maps[n,t] = sum_hd h[n,hd]*W2[n,t,hd] + b2[n,t];  lane = n*8+t
        {
            float acc = b2[lane];
            const int hb = (lane >> 3) * HID;
            const float* w2p = W2 + lane * HID;
#pragma unroll
            for (int hd = 0; hd < HID; hd++)
                acc += s_h[hb + hd] * w2p[hd];
            s_maps[lane] = acc * att_w[lane >> 3];
        }
        __syncwarp();
        if (lane == 0) {
            float w[T_STEPS];
            float mx = -1e30f;
#pragma unroll
            for (int t = 0; t < T_STEPS; t++) {
                w[t] = s_maps[t] + s_maps[8 + t] + s_maps[16 + t] + s_maps[24 + t];
                mx = fmaxf(mx, w[t]);
            }
            float ssum = 0.0f;
#pragma unroll
            for (int t = 0; t < T_STEPS; t++) { w[t] = expf(w[t] - mx); ssum += w[t]; }
            float inv = 1.0f / ssum;
#pragma unroll
            for (int t = 0; t < T_STEPS; t++) s_aw[t] = w[t] * inv;
        }
    }
    __syncthreads();

    float aw[T_STEPS];
#pragma unroll
    for (int t = 0; t < T_STEPS; t++) aw[t] = s_aw[t];

    // ---------------- output: out[b,f] = sum_t aw[t] * spike(t,f) ----------
    float4* op = reinterpret_cast<float4*>(out + (size_t)b * FDIM + f0);
#pragma unroll
    for (int k = 0; k < KG; k++) {
        unsigned int bt = bits4[k];
        float o[4];
#pragma unroll
        for (int j = 0; j < 4; j++) {
            float v = 0.0f;
#pragma unroll
            for (int t = 0; t < T_STEPS; t++)
                v += ((bt >> (8 * j + t)) & 1u) ? aw[t] : 0.0f;
            o[j] = v;
        }
        op[k * NTHREADS + tid] = make_float4(o[0], o[1], o[2], o[3]);
    }
}

extern "C" void kernel_launch(void* const* d_in, const int* in_sizes, int n_in,
                              void* d_out, int out_size) {
    (void)in_sizes; (void)n_in; (void)out_size;
    cudaFuncSetAttribute(bispike_kernel,
                         cudaFuncAttributeMaxDynamicSharedMemorySize,
                         EPB * (int)sizeof(float));
    reset_kernel<<<1, 32>>>();
    bispike_kernel<<<NBLOCKS, NTHREADS, EPB * sizeof(float)>>>(
        (const float*)d_in[0],   // x
        (const float*)d_in[1],   // decay_param
        (const float*)d_in[2],   // v_th
        (const float*)d_in[3],   // W1
        (const float*)d_in[4],   // b1
        (const float*)d_in[5],   // W2
        (const float*)d_in[6],   // b2
        (const float*)d_in[7],   // att_w
        (float*)d_out);
}

// round 2
// speedup vs baseline: 1.1116x; 1.1116x over previous
#include <cuda_runtime.h>

// ---------------------------------------------------------------------------
// BiSpikeNet forward, single persistent kernel. T=8, B=16, F=C*H*W=262144.
//
// 128 blocks (16 batches x 8 blocks/batch), 1024 threads. Membrane state in
// SMEM (128 KiB), packed spike bits in registers. The per-step mean(|m|) is
// PER-BATCH, so the software barrier spans only the 8 blocks of one batch
// (counters reset by a prologue kernel each launch -> graph-replay safe).
// While waiting at the barrier we prefetch x[t+1] into L2. Global traffic:
// read x (128 MiB) + write out (16 MiB) only.
// ---------------------------------------------------------------------------

namespace {
constexpr int T_STEPS        = 8;
constexpr int BATCH          = 16;
constexpr int FDIM           = 1 << 18;          // 262144
constexpr int BLKS_PER_BATCH = 8;
constexpr int NBLOCKS        = BATCH * BLKS_PER_BATCH;   // 128
constexpr int NTHREADS       = 1024;
constexpr int EPB            = FDIM / BLKS_PER_BATCH;    // 32768 elems/block
constexpr int KG             = EPB / (NTHREADS * 4);     // 8 float4 groups/thread
constexpr int NHEADS         = 4;
constexpr int HID            = 64;
constexpr int NBAR           = (T_STEPS + 1) * BATCH;    // 144 counters
}

__device__ unsigned int g_bar[NBAR];
__device__ float g_abs_part[T_STEPS][BATCH][BLKS_PER_BATCH];
__device__ int   g_cnt_part[T_STEPS][BATCH][BLKS_PER_BATCH];

__global__ void reset_kernel() {
    if (threadIdx.x < NBAR) g_bar[threadIdx.x] = 0u;
}

__device__ __forceinline__ void l2_prefetch(const void* p) {
    asm volatile("prefetch.global.L2 [%0];" :: "l"(p));
}

__global__ void __launch_bounds__(NTHREADS, 1) bispike_kernel(
    const float* __restrict__ x,
    const float* __restrict__ decay_p,
    const float* __restrict__ vth_p,
    const float* __restrict__ W1,
    const float* __restrict__ b1,
    const float* __restrict__ W2,
    const float* __restrict__ b2,
    const float* __restrict__ att_w,
    float* __restrict__ out)
{
    extern __shared__ float s_m[];               // EPB floats: membrane state
    __shared__ float s_red[32];
    __shared__ int   s_redi[32];
    __shared__ float s_h[NHEADS * HID];
    __shared__ float s_maps[32];
    __shared__ float s_aw[T_STEPS];
    __shared__ float s_invd;

    const int tid  = threadIdx.x;
    const int lane = tid & 31;
    const int warp = tid >> 5;
    const int b    = blockIdx.x >> 3;            // batch
    const int blk  = blockIdx.x & 7;             // slice within batch
    const int f0   = blk * EPB;

    const float d   = 1.0f / (1.0f + expf(-decay_p[0]));
    const float vth = vth_p[0];

    unsigned int bits4[KG];                      // 4 elems x 8 step-bits per word
#pragma unroll
    for (int k = 0; k < KG; k++) bits4[k] = 0u;

    float4* s_m4 = reinterpret_cast<float4*>(s_m);
    float inv_prev = 0.0f;

    const float* xbase = x + (size_t)b * FDIM + f0;

    // ---------------- temporal LIF loop ----------------
    for (int t = 0; t < T_STEPS; t++) {
        const float4* xp = reinterpret_cast<const float4*>(
            xbase + (size_t)t * BATCH * FDIM);
        float sa0 = 0.0f, sa1 = 0.0f, sa2 = 0.0f, sa3 = 0.0f;
        int   cnt_prev = 0;
#pragma unroll
        for (int k = 0; k < KG; k++) {
            const int idx4 = k * NTHREADS + tid;
            float4 xv = xp[idx4];
            float xa[4] = {xv.x, xv.y, xv.z, xv.w};
            float ma[4];
            if (t == 0) {
#pragma unroll
                for (int j = 0; j < 4; j++) ma[j] = xa[j];
            } else {
                float4 mo = s_m4[idx4];
                float moa[4] = {mo.x, mo.y, mo.z, mo.w};
#pragma unroll
                for (int j = 0; j < 4; j++) {
                    float mn = moa[j] * inv_prev;   // normalized m_{t-1}
                    bool  sp = (mn >= vth);
                    float sf = sp ? 1.0f : 0.0f;
                    if (sp) { bits4[k] |= (1u << (8 * j + (t - 1))); cnt_prev++; }
                    ma[j] = d * (mn - vth * sf) + xa[j];
                }
            }
            s_m4[idx4] = make_float4(ma[0], ma[1], ma[2], ma[3]);
            sa0 += fabsf(ma[0]); sa1 += fabsf(ma[1]);
            sa2 += fabsf(ma[2]); sa3 += fabsf(ma[3]);
        }
        float sum_abs = (sa0 + sa1) + (sa2 + sa3);

        // L2 prefetch of x[t+1] while we reduce + wait at the barrier.
        // One prefetch per 128B line: lanes 0,8,16,24 cover the warp's span.
        if (t + 1 < T_STEPS && (lane & 7) == 0) {
            const float4* xn = reinterpret_cast<const float4*>(
                xbase + (size_t)(t + 1) * BATCH * FDIM);
#pragma unroll
            for (int k = 0; k < KG; k++)
                l2_prefetch(&xn[k * NTHREADS + tid]);
        }

        // deterministic block reduction (|m| sum, previous-step spike count)
#pragma unroll
        for (int off = 16; off > 0; off >>= 1) {
            sum_abs  += __shfl_xor_sync(0xffffffffu, sum_abs, off);
            cnt_prev += __shfl_xor_sync(0xffffffffu, cnt_prev, off);
        }
        if (lane == 0) { s_red[warp] = sum_abs; s_redi[warp] = cnt_prev; }
        __syncthreads();
        if (warp == 0) {
            float v = s_red[lane];
            int   c = s_redi[lane];
#pragma unroll
            for (int off = 16; off > 0; off >>= 1) {
                v += __shfl_xor_sync(0xffffffffu, v, off);
                c += __shfl_xor_sync(0xffffffffu, c, off);
            }
            if (lane == 0) {
                g_abs_part[t][b][blk] = v;
                if (t > 0) g_cnt_part[t - 1][b][blk] = c;
                __threadfence();
                unsigned int* bar = &g_bar[t * BATCH + b];
                atomicAdd(bar, 1u);
                volatile unsigned int* ctr = bar;
                while (*ctr < (unsigned)BLKS_PER_BATCH) { }
                // deterministic 8-partial sum for this batch
                volatile float* pp = &g_abs_part[t][b][0];
                float tot = 0.0f;
#pragma unroll
                for (int i = 0; i < BLKS_PER_BATCH; i++) tot += pp[i];
                float denom = tot * (1.0f / (float)FDIM) + 1e-6f;
                s_invd = 1.0f / denom;
            }
        }
        __syncthreads();
        inv_prev = s_invd;
    }

    // ---------------- final step spikes (t = T-1) ----------------
    {
        int cnt = 0;
#pragma unroll
        for (int k = 0; k < KG; k++) {
            const int idx4 = k * NTHREADS + tid;
            float4 mo = s_m4[idx4];
            float moa[4] = {mo.x, mo.y, mo.z, mo.w};
#pragma unroll
            for (int j = 0; j < 4; j++) {
                if (moa[j] * inv_prev >= vth) {
                    bits4[k] |= (1u << (8 * j + 7));
                    cnt++;
                }
            }
        }
#pragma unroll
        for (int off = 16; off > 0; off >>= 1)
            cnt += __shfl_xor_sync(0xffffffffu, cnt, off);
        if (lane == 0) s_redi[warp] = cnt;
        __syncthreads();
        if (warp == 0) {
            int c = s_redi[lane];
#pragma unroll
            for (int off = 16; off > 0; off >>= 1)
                c += __shfl_xor_sync(0xffffffffu, c, off);
            if (lane == 0) {
                g_cnt_part[7][b][blk] = c;
                __threadfence();
                unsigned int* bar = &g_bar[T_STEPS * BATCH + b];
                atomicAdd(bar, 1u);
                volatile unsigned int* ctr = bar;
                while (*ctr < (unsigned)BLKS_PER_BATCH) { }
            }
        }
        __syncthreads();
    }

    // ---------------- tiny attention MLP (warp 0, per batch) ----------------
    if (warp == 0) {
        float summ[T_STEPS];
#pragma unroll
        for (int t = 0; t < T_STEPS; t++) {
            volatile int* cp = &g_cnt_part[t][b][0];
            int tot = 0;
#pragma unroll
            for (int i = 0; i < BLKS_PER_BATCH; i++) tot += cp[i];
            summ[t] = (float)tot * (1.0f / (float)FDIM);
        }
        // h[n,hd] = relu(sum_t summ[t]*W1[n,hd,t] + b1[n,hd]); 256 vals, 8/lane
#pragma unroll
        for (int r = 0; r < 8; r++) {
            int idx = r * 32 + lane;
            float acc = b1[idx];
#pragma unroll
            for (int t = 0; t < T_STEPS; t++)
                acc += summ[t] * W1[idx * T_STEPS + t];
            s_h[idx] = fmaxf(acc, 0.0f);
        }
        __syncwarp();
        // maps[n,t] = sum_hd h[n,hd]*W2[n,t,hd] + b2[n,t];  lane = n*8+t
        {
            float acc = b2[lane];
            const int hb = (lane >> 3) * HID;
            const float* w2p = W2 + lane * HID;
#pragma unroll
            for (int hd = 0; hd < HID; hd++)
                acc += s_h[hb + hd] * w2p[hd];
            s_maps[lane] = acc * att_w[lane >> 3];
        }
        __syncwarp();
        if (lane == 0) {
            float w[T_STEPS];
            float mx = -1e30f;
#pragma unroll
            for (int t = 0; t < T_STEPS; t++) {
                w[t] = s_maps[t] + s_maps[8 + t] + s_maps[16 + t] + s_maps[24 + t];
                mx = fmaxf(mx, w[t]);
            }
            float ssum = 0.0f;
#pragma unroll
            for (int t = 0; t < T_STEPS; t++) { w[t] = expf(w[t] - mx); ssum += w[t]; }
            float inv = 1.0f / ssum;
#pragma unroll
            for (int t = 0; t < T_STEPS; t++) s_aw[t] = w[t] * inv;
        }
    }
    __syncthreads();

    float aw[T_STEPS];
#pragma unroll
    for (int t = 0; t < T_STEPS; t++) aw[t] = s_aw[t];

    // ---------------- output: out[b,f] = sum_t aw[t] * spike(t,f) ----------
    float4* op = reinterpret_cast<float4*>(out + (size_t)b * FDIM + f0);
#pragma unroll
    for (int k = 0; k < KG; k++) {
        unsigned int bt = bits4[k];
        float o[4];
#pragma unroll
        for (int j = 0; j < 4; j++) {
            float v = 0.0f;
#pragma unroll
            for (int t = 0; t < T_STEPS; t++)
                v += ((bt >> (8 * j + t)) & 1u) ? aw[t] : 0.0f;
            o[j] = v;
        }
        op[k * NTHREADS + tid] = make_float4(o[0], o[1], o[2], o[3]);
    }
}

extern "C" void kernel_launch(void* const* d_in, const int* in_sizes, int n_in,
                              void* d_out, int out_size) {
    (void)in_sizes; (void)n_in; (void)out_size;
    cudaFuncSetAttribute(bispike_kernel,
                         cudaFuncAttributeMaxDynamicSharedMemorySize,
                         EPB * (int)sizeof(float));
    reset_kernel<<<1, 256>>>();
    bispike_kernel<<<NBLOCKS, NTHREADS, EPB * sizeof(float)>>>(
        (const float*)d_in[0],   // x
        (const float*)d_in[1],   // decay_param
        (const float*)d_in[2],   // v_th
        (const float*)d_in[3],   // W1
        (const float*)d_in[4],   // b1
        (const float*)d_in[5],   // W2
        (const float*)d_in[6],   // b2
        (const float*)d_in[7],   // att_w
        (float*)d_out);
}